// round 6
// baseline (speedup 1.0000x reference)
#include <cuda_runtime.h>
#include <cuda_bf16.h>
#include <stdint.h>
#include <math.h>

// Shapes (fixed for this problem)
#define B_  16
#define S_  512
#define E_  128
#define T_  640      // S_ + E_
#define D_  768
#define H_  12
#define DH_ 64
#define FF_ 3072
#define NT_ (B_*T_) // 10240

typedef __nv_bfloat16 bf16;
typedef unsigned int       u32;
typedef unsigned long long u64;

// ---------------- scratch (__device__ globals) ------------------------------
__device__ float g_ao [(size_t)NT_*D_];
__device__ float g_tmp[(size_t)NT_*D_];

__device__ bf16 g_word_h[(size_t)B_*S_*D_], g_word_l[(size_t)B_*S_*D_];
__device__ bf16 g_ent_h [(size_t)B_*E_*D_], g_ent_l [(size_t)B_*E_*D_];
__device__ bf16 g_q1h[(size_t)NT_*D_], g_q1l[(size_t)NT_*D_];
__device__ bf16 g_q2h[(size_t)NT_*D_], g_q2l[(size_t)NT_*D_];
__device__ bf16 g_kh [(size_t)NT_*D_], g_kl [(size_t)NT_*D_];
__device__ bf16 g_vh [(size_t)NT_*D_], g_vl [(size_t)NT_*D_];
__device__ bf16 g_ctx_h[(size_t)NT_*D_], g_ctx_l[(size_t)NT_*D_];
__device__ bf16 g_ao_h [(size_t)NT_*D_], g_ao_l [(size_t)NT_*D_];
__device__ bf16 g_int_h[(size_t)NT_*FF_], g_int_l[(size_t)NT_*FF_];

// packed split weights ([N,K] row-major)
__device__ bf16 g_wpw_h[4*D_*D_], g_wpw_l[4*D_*D_];   // word: q | w2e | k | v
__device__ bf16 g_wpe_h[4*D_*D_], g_wpe_l[4*D_*D_];   // ent:  e2w | e2e | k | v
__device__ bf16 g_wao_h[D_*D_],  g_wao_l[D_*D_];
__device__ bf16 g_wi_h [FF_*D_], g_wi_l [FF_*D_];
__device__ bf16 g_wo_h [D_*FF_], g_wo_l [D_*FF_];

struct DestPack { float* y; bf16* yh; bf16* yl; const float* bias; };
struct Dest4 { DestPack d[4]; };

// ---------------- PTX helpers ----------------------------------------------
__device__ __forceinline__ u32 smem_u32(const void* p) {
    u32 a;
    asm("{ .reg .u64 t; cvta.to.shared.u64 t, %1; cvt.u32.u64 %0, t; }" : "=r"(a) : "l"(p));
    return a;
}
__device__ __forceinline__ void cpa16(u32 s, const void* g) {
    asm volatile("cp.async.cg.shared.global [%0], [%1], 16;" :: "r"(s), "l"(g));
}
__device__ __forceinline__ void ldsm4(u32 addr, u32& r0, u32& r1, u32& r2, u32& r3) {
    asm volatile("ldmatrix.sync.aligned.m8n8.x4.shared.b16 {%0,%1,%2,%3}, [%4];"
                 : "=r"(r0), "=r"(r1), "=r"(r2), "=r"(r3) : "r"(addr));
}
__device__ __forceinline__ void ldsm4t(u32 addr, u32& r0, u32& r1, u32& r2, u32& r3) {
    asm volatile("ldmatrix.sync.aligned.m8n8.x4.trans.shared.b16 {%0,%1,%2,%3}, [%4];"
                 : "=r"(r0), "=r"(r1), "=r"(r2), "=r"(r3) : "r"(addr));
}
__device__ __forceinline__ void mma16816(float* c, const u32* a, u32 b0, u32 b1) {
    asm volatile(
        "mma.sync.aligned.m16n8k16.row.col.f32.bf16.bf16.f32 "
        "{%0,%1,%2,%3}, {%4,%5,%6,%7}, {%8,%9}, {%0,%1,%2,%3};"
        : "+f"(c[0]), "+f"(c[1]), "+f"(c[2]), "+f"(c[3])
        : "r"(a[0]), "r"(a[1]), "r"(a[2]), "r"(a[3]), "r"(b0), "r"(b1));
}
__device__ __forceinline__ float fexp(float x) {
    x = fmaxf(x, -80.f);
    float y = x * 1.4426950408889634f;
    int n = __float2int_rn(y);
    float f = y - (float)n;
    float p = 1.33336e-3f;
    p = fmaf(p, f, 9.61813e-3f);
    p = fmaf(p, f, 5.5504109e-2f);
    p = fmaf(p, f, 2.4022651e-1f);
    p = fmaf(p, f, 6.9314718e-1f);
    p = fmaf(p, f, 1.0f);
    return p * __int_as_float((n + 127) << 23);
}
__device__ __forceinline__ u32 pack_bf2(float a, float b) {
    __nv_bfloat162 t = __floats2bfloat162_rn(a, b);
    return *(u32*)&t;
}
__device__ __forceinline__ float bf_lo(float v) {
    return v - __bfloat162float(__float2bfloat16(v));
}

// ---------------- weight transpose + split ----------------------------------
__global__ __launch_bounds__(256)
void wconv(const float* __restrict__ W, bf16* __restrict__ th, bf16* __restrict__ tl,
           int K, int N)
{
    __shared__ float t[32][33];
    const int n0 = blockIdx.x * 32, k0 = blockIdx.y * 32;
    const int tx = threadIdx.x & 31, ty = threadIdx.x >> 5;
#pragma unroll
    for (int i = 0; i < 4; i++)
        t[ty + i*8][tx] = W[(size_t)(k0 + ty + i*8) * N + n0 + tx];
    __syncthreads();
#pragma unroll
    for (int i = 0; i < 4; i++) {
        float v = t[tx][ty + i*8];
        bf16 h = __float2bfloat16(v);
        size_t o = (size_t)(n0 + ty + i*8) * K + k0 + tx;
        th[o] = h;
        tl[o] = __float2bfloat16(v - __bfloat162float(h));
    }
}

// ---------------- activation split ------------------------------------------
__global__ __launch_bounds__(256)
void aconv(const float* __restrict__ x, bf16* __restrict__ h, bf16* __restrict__ l)
{
    size_t i = (size_t)blockIdx.x * 256 + threadIdx.x;
    float v = x[i];
    bf16 hi = __float2bfloat16(v);
    h[i] = hi;
    l[i] = __float2bfloat16(v - __bfloat162float(hi));
}

// ---------------- mma.sync split-bf16 GEMM (128x256 CTA, 64x64 warp) ---------
// Y[m,n] = A[m,:] @ Bt[n,:] + bias   dest selected by n / nsplit (row stride nsplit)
// act==0: fp32 out. act==1: GELU + split out. act==2: bias + split out.
#define BK_      32
#define AROW_BY  80
#define ATILE_BY (128*AROW_BY)       // 10240
#define BTILE_BY (256*AROW_BY)       // 20480
#define STG_BY   (2*ATILE_BY + 2*BTILE_BY)   // 61440
#define SMEM_DYN (3*STG_BY)                  // 184320

__global__ __launch_bounds__(256, 1)
void gemm_tc(const bf16* __restrict__ Ah, const bf16* __restrict__ Al,
             const bf16* __restrict__ Bh, const bf16* __restrict__ Bl,
             Dest4 dp, int M, int N, int K, int nsplit, int seg, int rowoff, int act)
{
    extern __shared__ char smem[];
    const u32 sb = smem_u32(smem);
    const int tid  = threadIdx.x;
    const int lane = tid & 31;
    const int wid  = tid >> 5;
    const int wm   = wid >> 2;     // 0..1
    const int wn   = wid & 3;      // 0..3
    const int n0 = blockIdx.x * 256;
    const int m0 = blockIdx.y * 128;
    const int nk = K / BK_;

    auto load_chunk = [&](int s, int kc) {
        const int k0c = kc * BK_;
        const u32 stg = sb + (u32)s * STG_BY;
#pragma unroll
        for (int i = 0; i < 12; i++) {
            int idx = tid + i * 256;          // 0..3071
            int r   = idx >> 2;
            int c16 = idx & 3;
            const bf16* g; u32 soff;
            if (r < 128)      { g = Ah + (size_t)(m0 + r) * K;        soff = (u32)(r * 80); }
            else if (r < 256) { g = Al + (size_t)(m0 + r - 128) * K;  soff = 10240u + (u32)((r - 128) * 80); }
            else if (r < 512) { g = Bh + (size_t)(n0 + r - 256) * K;  soff = 20480u + (u32)((r - 256) * 80); }
            else              { g = Bl + (size_t)(n0 + r - 512) * K;  soff = 40960u + (u32)((r - 512) * 80); }
            cpa16(stg + soff + (u32)(c16 * 16), g + k0c + c16 * 8);
        }
        asm volatile("cp.async.commit_group;" ::: "memory");
    };

    float acc[4][8][4];
#pragma unroll
    for (int mt = 0; mt < 4; mt++)
#pragma unroll
        for (int nt = 0; nt < 8; nt++)
#pragma unroll
            for (int j = 0; j < 4; j++) acc[mt][nt][j] = 0.f;

    const u32 frag_row = (u32)(lane & 15);
    const u32 frag_col = (u32)((lane >> 4) << 4);

    load_chunk(0, 0);
    load_chunk(1, 1);

    for (int kc = 0; kc < nk; kc++) {
        const int s = kc % 3;
        if (kc + 2 < nk) {
            load_chunk((kc + 2) % 3, kc + 2);
            asm volatile("cp.async.wait_group 2;" ::: "memory");
        } else if (kc + 1 < nk) {
            asm volatile("cp.async.wait_group 1;" ::: "memory");
        } else {
            asm volatile("cp.async.wait_group 0;" ::: "memory");
        }
        __syncthreads();

        const u32 stg = sb + (u32)s * STG_BY;
        const u32 aBaseH = stg;
        const u32 aBaseL = stg + 10240u;
        const u32 bBaseH = stg + 20480u;
        const u32 bBaseL = stg + 40960u;

#pragma unroll
        for (int ks = 0; ks < 2; ks++) {
            const u32 kByte = (u32)(ks * 32) + frag_col;
            u32 ah[4][4], al[4][4], bh[4][4], bl[4][4];
#pragma unroll
            for (int mt = 0; mt < 4; mt++) {
                u32 ro = (u32)(wm * 64 + mt * 16) + frag_row;
                ldsm4(aBaseH + ro * 80 + kByte, ah[mt][0], ah[mt][1], ah[mt][2], ah[mt][3]);
                ldsm4(aBaseL + ro * 80 + kByte, al[mt][0], al[mt][1], al[mt][2], al[mt][3]);
            }
#pragma unroll
            for (int np = 0; np < 4; np++) {
                u32 ro = (u32)(wn * 64 + np * 16) + frag_row;
                ldsm4(bBaseH + ro * 80 + kByte, bh[np][0], bh[np][1], bh[np][2], bh[np][3]);
                ldsm4(bBaseL + ro * 80 + kByte, bl[np][0], bl[np][1], bl[np][2], bl[np][3]);
            }
#pragma unroll
            for (int mt = 0; mt < 4; mt++)
#pragma unroll
                for (int nt = 0; nt < 8; nt++) {
                    int np = nt >> 1, sel = nt & 1;
                    u32 b0h = bh[np][sel], b1h = bh[np][sel + 2];
                    u32 b0l = bl[np][sel], b1l = bl[np][sel + 2];
                    mma16816(acc[mt][nt], ah[mt], b0h, b1h);
                    mma16816(acc[mt][nt], ah[mt], b0l, b1l);
                    mma16816(acc[mt][nt], al[mt], b0h, b1h);
                }
        }
        __syncthreads();
    }

    // epilogue: dest selected by n-block
    const int di = n0 / nsplit;
    float* Y  = dp.d[di].y;
    bf16* Yh  = dp.d[di].yh;
    bf16* Yl  = dp.d[di].yl;
    const float* bias = dp.d[di].bias;
    const int ncol_off = di * nsplit;

#pragma unroll
    for (int mt = 0; mt < 4; mt++) {
#pragma unroll
        for (int half = 0; half < 2; half++) {
            int mlog = m0 + wm * 64 + mt * 16 + (lane >> 2) + half * 8;
            size_t phys = (size_t)(mlog / seg) * T_ + (mlog % seg) + rowoff;
#pragma unroll
            for (int nt = 0; nt < 8; nt++) {
                int col = n0 + wn * 64 + nt * 8 + (lane & 3) * 2 - ncol_off;
                float v0 = acc[mt][nt][half * 2 + 0] + bias[col + 0];
                float v1 = acc[mt][nt][half * 2 + 1] + bias[col + 1];
                if (act == 0) {
                    *(float2*)(Y + phys * (size_t)nsplit + col) = make_float2(v0, v1);
                } else {
                    if (act == 1) {
                        v0 = 0.5f * v0 * (1.0f + erff(v0 * 0.70710678f));
                        v1 = 0.5f * v1 * (1.0f + erff(v1 * 0.70710678f));
                    }
                    *(u32*)(Yh + phys * (size_t)nsplit + col) = pack_bf2(v0, v1);
                    *(u32*)(Yl + phys * (size_t)nsplit + col) = pack_bf2(bf_lo(v0), bf_lo(v1));
                }
            }
        }
    }
}

// ---------------- tensor-core flash attention --------------------------------
#define QT_BY   (128*144)
#define A_Q1H   0
#define A_Q1L   (1*QT_BY)
#define A_Q2H   (2*QT_BY)
#define A_Q2L   (3*QT_BY)
#define A_KH    (4*QT_BY)
#define A_KL    (5*QT_BY)
#define A_VH    (6*QT_BY)
#define A_VL    (7*QT_BY)
#define A_MS    (8*QT_BY)
#define ATT_SMEM (8*QT_BY + 512)

__global__ __launch_bounds__(256, 1)
void attn_tc(const bf16* __restrict__ q1h, const bf16* __restrict__ q1l,
             const bf16* __restrict__ q2h, const bf16* __restrict__ q2l,
             const bf16* __restrict__ kh,  const bf16* __restrict__ kl,
             const bf16* __restrict__ vh,  const bf16* __restrict__ vl,
             const float* __restrict__ mask,
             bf16* __restrict__ ctxH, bf16* __restrict__ ctxL)
{
    extern __shared__ char smem[];
    const u32 sb = smem_u32(smem);
    float* maskS = (float*)(smem + A_MS);

    const int b  = blockIdx.z;
    const int h  = blockIdx.y;
    const int q0 = blockIdx.x * 128;
    const int tid  = threadIdx.x;
    const int lane = tid & 31;
    const int w    = tid >> 5;

    const u32 frag_row = (u32)(lane & 15);
    const u32 frag_col = (u32)((lane >> 4) << 4);

    {
        const bf16* srcQ[4] = { q1h, q1l, q2h, q2l };
#pragma unroll
        for (int i = 0; i < 16; i++) {
            int idx = tid + i * 256;
            int arr = idx >> 10;
            int rr  = (idx >> 3) & 127;
            int ch  = idx & 7;
            cpa16(sb + (u32)(arr * QT_BY + rr * 144 + ch * 16),
                  srcQ[arr] + (size_t)(b * T_ + q0 + rr) * D_ + h * DH_ + ch * 8);
        }
        asm volatile("cp.async.commit_group;" ::: "memory");
    }

    float Oa[8][4];
#pragma unroll
    for (int od = 0; od < 8; od++)
#pragma unroll
        for (int j = 0; j < 4; j++) Oa[od][j] = 0.f;
    float m0 = -1e30f, m1 = -1e30f, l0 = 0.f, l1 = 0.f;

    for (int kt = 0; kt < 5; kt++) {
        __syncthreads();
        {
            const bf16* srcT[4] = { kh, kl, vh, vl };
#pragma unroll
            for (int i = 0; i < 16; i++) {
                int idx = tid + i * 256;
                int arr = idx >> 10;
                int rr  = (idx >> 3) & 127;
                int ch  = idx & 7;
                cpa16(sb + (u32)(A_KH + arr * QT_BY + rr * 144 + ch * 16),
                      srcT[arr] + (size_t)(b * T_ + kt * 128 + rr) * D_ + h * DH_ + ch * 8);
            }
            if (tid < 128) maskS[tid] = mask[b * T_ + kt * 128 + tid];
            asm volatile("cp.async.commit_group;" ::: "memory");
            asm volatile("cp.async.wait_group 0;" ::: "memory");
        }
        __syncthreads();

        const u32 qbh = sb + (u32)((kt < 4) ? A_Q1H : A_Q2H);
        const u32 qbl = qbh + QT_BY;

        float sc_[16][4];
#pragma unroll
        for (int nt = 0; nt < 16; nt++)
#pragma unroll
            for (int j = 0; j < 4; j++) sc_[nt][j] = 0.f;

#pragma unroll
        for (int ks = 0; ks < 4; ks++) {
            const u32 kByte = (u32)(ks * 32) + frag_col;
            u32 ah[4], al[4], bh[8][4], bl[8][4];
            u32 ro = (u32)(w * 16) + frag_row;
            ldsm4(qbh + ro * 144 + kByte, ah[0], ah[1], ah[2], ah[3]);
            ldsm4(qbl + ro * 144 + kByte, al[0], al[1], al[2], al[3]);
#pragma unroll
            for (int np = 0; np < 8; np++) {
                u32 kr = (u32)(np * 16) + frag_row;
                ldsm4(sb + A_KH + kr * 144 + kByte, bh[np][0], bh[np][1], bh[np][2], bh[np][3]);
                ldsm4(sb + A_KL + kr * 144 + kByte, bl[np][0], bl[np][1], bl[np][2], bl[np][3]);
            }
#pragma unroll
            for (int nt = 0; nt < 16; nt++) {
                int np = nt >> 1, sel = nt & 1;
                u32 b0h = bh[np][sel], b1h = bh[np][sel + 2];
                u32 b0l = bl[np][sel], b1l = bl[np][sel + 2];
                mma16816(sc_[nt], ah, b0h, b1h);
                mma16816(sc_[nt], ah, b0l, b1l);
                mma16816(sc_[nt], al, b0h, b1h);
            }
        }

        float rmax0 = -1e30f, rmax1 = -1e30f;
#pragma unroll
        for (int nt = 0; nt < 16; nt++) {
            int cbase = nt * 8 + (lane & 3) * 2;
            float mk0 = maskS[cbase], mk1 = maskS[cbase + 1];
            sc_[nt][0] = fmaf(sc_[nt][0], 0.125f, mk0);
            sc_[nt][1] = fmaf(sc_[nt][1], 0.125f, mk1);
            sc_[nt][2] = fmaf(sc_[nt][2], 0.125f, mk0);
            sc_[nt][3] = fmaf(sc_[nt][3], 0.125f, mk1);
            rmax0 = fmaxf(rmax0, fmaxf(sc_[nt][0], sc_[nt][1]));
            rmax1 = fmaxf(rmax1, fmaxf(sc_[nt][2], sc_[nt][3]));
        }
        rmax0 = fmaxf(rmax0, __shfl_xor_sync(0xffffffffu, rmax0, 1));
        rmax0 = fmaxf(rmax0, __shfl_xor_sync(0xffffffffu, rmax0, 2));
        rmax1 = fmaxf(rmax1, __shfl_xor_sync(0xffffffffu, rmax1, 1));
        rmax1 = fmaxf(rmax1, __shfl_xor_sync(0xffffffffu, rmax1, 2));

        float mn0 = fmaxf(m0, rmax0), mn1 = fmaxf(m1, rmax1);
        float f0 = fexp(m0 - mn0), f1 = fexp(m1 - mn1);
        float rs0 = 0.f, rs1 = 0.f;
#pragma unroll
        for (int nt = 0; nt < 16; nt++) {
            sc_[nt][0] = fexp(sc_[nt][0] - mn0);
            sc_[nt][1] = fexp(sc_[nt][1] - mn0);
            sc_[nt][2] = fexp(sc_[nt][2] - mn1);
            sc_[nt][3] = fexp(sc_[nt][3] - mn1);
            rs0 += sc_[nt][0] + sc_[nt][1];
            rs1 += sc_[nt][2] + sc_[nt][3];
        }
        rs0 += __shfl_xor_sync(0xffffffffu, rs0, 1);
        rs0 += __shfl_xor_sync(0xffffffffu, rs0, 2);
        rs1 += __shfl_xor_sync(0xffffffffu, rs1, 1);
        rs1 += __shfl_xor_sync(0xffffffffu, rs1, 2);
        l0 = l0 * f0 + rs0;
        l1 = l1 * f1 + rs1;
        m0 = mn0; m1 = mn1;
#pragma unroll
        for (int od = 0; od < 8; od++) {
            Oa[od][0] *= f0; Oa[od][1] *= f0;
            Oa[od][2] *= f1; Oa[od][3] *= f1;
        }

#pragma unroll
        for (int ks2 = 0; ks2 < 8; ks2++) {
            float p00 = sc_[2*ks2][0],   p01 = sc_[2*ks2][1];
            float p02 = sc_[2*ks2][2],   p03 = sc_[2*ks2][3];
            float p10 = sc_[2*ks2+1][0], p11 = sc_[2*ks2+1][1];
            float p12 = sc_[2*ks2+1][2], p13 = sc_[2*ks2+1][3];
            u32 aPh[4], aPl[4];
            aPh[0] = pack_bf2(p00, p01);
            aPh[1] = pack_bf2(p02, p03);
            aPh[2] = pack_bf2(p10, p11);
            aPh[3] = pack_bf2(p12, p13);
            aPl[0] = pack_bf2(bf_lo(p00), bf_lo(p01));
            aPl[1] = pack_bf2(bf_lo(p02), bf_lo(p03));
            aPl[2] = pack_bf2(bf_lo(p10), bf_lo(p11));
            aPl[3] = pack_bf2(bf_lo(p12), bf_lo(p13));

            const u32 vr = (u32)(ks2 * 16) + frag_row;
#pragma unroll
            for (int nd = 0; nd < 4; nd++) {
                const u32 cByte = (u32)(nd * 32) + frag_col;
                u32 vh0, vh1, vh2, vh3, vl0, vl1, vl2, vl3;
                ldsm4t(sb + A_VH + vr * 144 + cByte, vh0, vh1, vh2, vh3);
                ldsm4t(sb + A_VL + vr * 144 + cByte, vl0, vl1, vl2, vl3);
                int od0 = nd * 2, od1 = nd * 2 + 1;
                mma16816(Oa[od0], aPh, vh0, vh1);
                mma16816(Oa[od0], aPh, vl0, vl1);
                mma16816(Oa[od0], aPl, vh0, vh1);
                mma16816(Oa[od1], aPh, vh2, vh3);
                mma16816(Oa[od1], aPh, vl2, vl3);
                mma16816(Oa[od1], aPl, vh2, vh3);
            }
        }
    }

    float inv0 = 1.f / l0, inv1 = 1.f / l1;
    int qa = q0 + w * 16 + (lane >> 2);
    int qb = qa + 8;
    size_t baseA = (size_t)(b * T_ + qa) * D_ + h * DH_;
    size_t baseB = (size_t)(b * T_ + qb) * D_ + h * DH_;
#pragma unroll
    for (int od = 0; od < 8; od++) {
        int col = od * 8 + (lane & 3) * 2;
        float o0 = Oa[od][0] * inv0, o1 = Oa[od][1] * inv0;
        float o2 = Oa[od][2] * inv1, o3 = Oa[od][3] * inv1;
        *(u32*)(ctxH + baseA + col) = pack_bf2(o0, o1);
        *(u32*)(ctxL + baseA + col) = pack_bf2(bf_lo(o0), bf_lo(o1));
        *(u32*)(ctxH + baseB + col) = pack_bf2(o2, o3);
        *(u32*)(ctxL + baseB + col) = pack_bf2(bf_lo(o2), bf_lo(o3));
    }
}

// ---------------- residual + LayerNorm ---------------------------------------
__global__ __launch_bounds__(256)
void ln_kernel(const float* __restrict__ raw,
               const float* __restrict__ rw, const float* __restrict__ re,
               const float* __restrict__ rfull, int use_full,
               const float* __restrict__ gm, const float* __restrict__ bt,
               float* __restrict__ out, int final_mode,
               bf16* __restrict__ outH, bf16* __restrict__ outL)
{
    const int row = blockIdx.x;
    const int b = row / T_, t = row % T_;
    const float* rp = use_full
        ? rfull + (size_t)row * D_
        : (t < S_ ? rw + ((size_t)(b * S_ + t)) * D_
                  : re + ((size_t)(b * E_ + t - S_)) * D_);
    const float* x = raw + (size_t)row * D_;

    float vv[3];
    float s = 0.f, sq = 0.f;
#pragma unroll
    for (int i = 0; i < 3; i++) {
        int c = threadIdx.x + i * 256;
        float val = x[c] + rp[c];
        vv[i] = val;
        s += val;
        sq += val * val;
    }
    const int lane = threadIdx.x & 31, w = threadIdx.x >> 5;
#pragma unroll
    for (int o = 16; o; o >>= 1) {
        s  += __shfl_xor_sync(0xffffffffu, s,  o);
        sq += __shfl_xor_sync(0xffffffffu, sq, o);
    }
    __shared__ float ws[8], wq[8];
    __shared__ float sm, sv;
    if (lane == 0) { ws[w] = s; wq[w] = sq; }
    __syncthreads();
    if (threadIdx.x == 0) {
        float ts = 0.f, tq = 0.f;
#pragma unroll
        for (int i = 0; i < 8; i++) { ts += ws[i]; tq += wq[i]; }
        float mean = ts * (1.f / D_);
        sm = mean;
        sv = rsqrtf(tq * (1.f / D_) - mean * mean + 1e-12f);
    }
    __syncthreads();
    const float mean = sm, inv = sv;

    float* o = final_mode
        ? (t < S_ ? out + ((size_t)(b * S_ + t)) * D_
                  : out + (size_t)B_ * S_ * D_ + ((size_t)(b * E_ + t - S_)) * D_)
        : out + (size_t)row * D_;
#pragma unroll
    for (int i = 0; i < 3; i++) {
        int c = threadIdx.x + i * 256;
        float y = (vv[i] - mean) * inv * gm[c] + bt[c];
        o[c] = y;
        if (outH) {
            bf16 h = __float2bfloat16(y);
            outH[(size_t)row * D_ + c] = h;
            outL[(size_t)row * D_ + c] = __float2bfloat16(y - __bfloat162float(h));
        }
    }
}

// ---------------- host -------------------------------------------------------
extern "C" void kernel_launch(void* const* d_in, const int* in_sizes, int n_in,
                              void* d_out, int out_size)
{
    const float* word  = (const float*)d_in[0];
    const float* ent   = (const float*)d_in[1];
    const float* mask  = (const float*)d_in[2];
    const float* W_q   = (const float*)d_in[3],  *b_q    = (const float*)d_in[4];
    const float* W_k   = (const float*)d_in[5],  *b_k    = (const float*)d_in[6];
    const float* W_v   = (const float*)d_in[7],  *b_v    = (const float*)d_in[8];
    const float* W_w2e = (const float*)d_in[9],  *b_w2e  = (const float*)d_in[10];
    const float* W_e2w = (const float*)d_in[11], *b_e2w  = (const float*)d_in[12];
    const float* W_e2e = (const float*)d_in[13], *b_e2e  = (const float*)d_in[14];
    const float* W_ao  = (const float*)d_in[15], *b_ao   = (const float*)d_in[16];
    const float* gm_ao = (const float*)d_in[17], *bt_ao  = (const float*)d_in[18];
    const float* W_i   = (const float*)d_in[19], *b_i    = (const float*)d_in[20];
    const float* W_o   = (const float*)d_in[21], *b_o    = (const float*)d_in[22];
    const float* gm_o  = (const float*)d_in[23], *bt_o   = (const float*)d_in[24];

    void* p;
    cudaGetSymbolAddress(&p, g_ao);    float* d_ao  = (float*)p;
    cudaGetSymbolAddress(&p, g_tmp);   float* d_tmp = (float*)p;

    bf16 *wordH,*wordL,*entH,*entL,*q1H,*q1L,*q2H,*q2L,*kH,*kL,*vH,*vL,*ctxH,*ctxL,*aoH,*aoL,*intH,*intL;
    cudaGetSymbolAddress(&p, g_word_h); wordH = (bf16*)p;
    cudaGetSymbolAddress(&p, g_word_l); wordL = (bf16*)p;
    cudaGetSymbolAddress(&p, g_ent_h);  entH  = (bf16*)p;
    cudaGetSymbolAddress(&p, g_ent_l);  entL  = (bf16*)p;
    cudaGetSymbolAddress(&p, g_q1h);    q1H   = (bf16*)p;
    cudaGetSymbolAddress(&p, g_q1l);    q1L   = (bf16*)p;
    cudaGetSymbolAddress(&p, g_q2h);    q2H   = (bf16*)p;
    cudaGetSymbolAddress(&p, g_q2l);    q2L   = (bf16*)p;
    cudaGetSymbolAddress(&p, g_kh);     kH    = (bf16*)p;
    cudaGetSymbolAddress(&p, g_kl);     kL    = (bf16*)p;
    cudaGetSymbolAddress(&p, g_vh);     vH    = (bf16*)p;
    cudaGetSymbolAddress(&p, g_vl);     vL    = (bf16*)p;
    cudaGetSymbolAddress(&p, g_ctx_h);  ctxH  = (bf16*)p;
    cudaGetSymbolAddress(&p, g_ctx_l);  ctxL  = (bf16*)p;
    cudaGetSymbolAddress(&p, g_ao_h);   aoH   = (bf16*)p;
    cudaGetSymbolAddress(&p, g_ao_l);   aoL   = (bf16*)p;
    cudaGetSymbolAddress(&p, g_int_h);  intH  = (bf16*)p;
    cudaGetSymbolAddress(&p, g_int_l);  intL  = (bf16*)p;

    bf16 *wpwH,*wpwL,*wpeH,*wpeL,*waoH,*waoL,*wiH,*wiL,*woH,*woL;
    cudaGetSymbolAddress(&p, g_wpw_h); wpwH = (bf16*)p;
    cudaGetSymbolAddress(&p, g_wpw_l); wpwL = (bf16*)p;
    cudaGetSymbolAddress(&p, g_wpe_h); wpeH = (bf16*)p;
    cudaGetSymbolAddress(&p, g_wpe_l); wpeL = (bf16*)p;
    cudaGetSymbolAddress(&p, g_wao_h); waoH = (bf16*)p;
    cudaGetSymbolAddress(&p, g_wao_l); waoL = (bf16*)p;
    cudaGetSymbolAddress(&p, g_wi_h);  wiH  = (bf16*)p;
    cudaGetSymbolAddress(&p, g_wi_l);  wiL  = (bf16*)p;
    cudaGetSymbolAddress(&p, g_wo_h);  woH  = (bf16*)p;
    cudaGetSymbolAddress(&p, g_wo_l);  woL  = (bf16*)p;

    cudaFuncSetAttribute(gemm_tc, cudaFuncAttributeMaxDynamicSharedMemorySize, SMEM_DYN);
    cudaFuncSetAttribute(attn_tc, cudaFuncAttributeMaxDynamicSharedMemorySize, ATT_SMEM);

    const dim3 thr(256);
    const int MW = B_ * S_;
    const int ME = B_ * E_;
    const size_t WSLICE = (size_t)D_ * D_;   // 768*768

    // weight transpose+split into packed buffers
    wconv<<<dim3(D_/32,  D_/32),  thr>>>(W_q,   wpwH + 0*WSLICE, wpwL + 0*WSLICE, D_, D_);
    wconv<<<dim3(D_/32,  D_/32),  thr>>>(W_w2e, wpwH + 1*WSLICE, wpwL + 1*WSLICE, D_, D_);
    wconv<<<dim3(D_/32,  D_/32),  thr>>>(W_k,   wpwH + 2*WSLICE, wpwL + 2*WSLICE, D_, D_);
    wconv<<<dim3(D_/32,  D_/32),  thr>>>(W_v,   wpwH + 3*WSLICE, wpwL + 3*WSLICE, D_, D_);
    wconv<<<dim3(D_/32,  D_/32),  thr>>>(W_e2w, wpeH + 0*WSLICE, wpeL + 0*WSLICE, D_, D_);
    wconv<<<dim3(D_/32,  D_/32),  thr>>>(W_e2e, wpeH + 1*WSLICE, wpeL + 1*WSLICE, D_, D_);
    wconv<<<dim3(D_/32,  D_/32),  thr>>>(W_k,   wpeH + 2*WSLICE, wpeL + 2*WSLICE, D_, D_);
    wconv<<<dim3(D_/32,  D_/32),  thr>>>(W_v,   wpeH + 3*WSLICE, wpeL + 3*WSLICE, D_, D_);
    wconv<<<dim3(D_/32,  D_/32),  thr>>>(W_ao,  waoH, waoL, D_,  D_);
    wconv<<<dim3(FF_/32, D_/32),  thr>>>(W_i,   wiH,  wiL,  D_,  FF_);
    wconv<<<dim3(D_/32,  FF_/32), thr>>>(W_o,   woH,  woL,  FF_, D_);

    aconv<<<(unsigned)((size_t)MW * D_ / 256), thr>>>(word, wordH, wordL);
    aconv<<<(unsigned)((size_t)ME * D_ / 256), thr>>>(ent,  entH,  entL);

    // packed projections (word + entity), interleaved into [B,T,D]
    Dest4 dpW;
    dpW.d[0] = { nullptr, q1H, q1L, b_q   };
    dpW.d[1] = { nullptr, q2H, q2L, b_w2e };
    dpW.d[2] = { nullptr, kH,  kL,  b_k   };
    dpW.d[3] = { nullptr, vH,  vL,  b_v   };
    gemm_tc<<<dim3(4*D_/256, MW/128), thr, SMEM_DYN>>>(wordH, wordL, wpwH, wpwL,
        dpW, MW, 4*D_, D_, D_, S_, 0, 2);

    Dest4 dpE;
    dpE.d[0] = { nullptr, q1H, q1L, b_e2w };
    dpE.d[1] = { nullptr, q2H, q2L, b_e2e };
    dpE.d[2] = { nullptr, kH,  kL,  b_k   };
    dpE.d[3] = { nullptr, vH,  vL,  b_v   };
    gemm_tc<<<dim3(4*D_/256, ME/128), thr, SMEM_DYN>>>(entH, entL, wpeH, wpeL,
        dpE, ME, 4*D_, D_, D_, E_, S_, 2);

    // attention -> split ctx
    attn_tc<<<dim3(T_/128, H_, B_), thr, ATT_SMEM>>>(q1H, q1L, q2H, q2L, kH, kL, vH, vL,
                                                     mask, ctxH, ctxL);

    // AO projection + LN
    Dest4 dpA;
    dpA.d[0] = { d_tmp, nullptr, nullptr, b_ao };
    dpA.d[1] = dpA.d[0]; dpA.d[2] = dpA.d[0]; dpA.d[3] = dpA.d[0];
    gemm_tc<<<dim3(D_/256, NT_/128), thr, SMEM_DYN>>>(ctxH, ctxL, waoH, waoL,
        dpA, NT_, D_, D_, D_, NT_, 0, 0);
    ln_kernel<<<NT_, thr>>>(d_tmp, word, ent, d_ao, 0, gm_ao, bt_ao, d_ao, 0, aoH, aoL);

    // FFN1 (+GELU, split out)
    Dest4 dpI;
    dpI.d[0] = { nullptr, intH, intL, b_i };
    dpI.d[1] = dpI.d[0]; dpI.d[2] = dpI.d[0]; dpI.d[3] = dpI.d[0];
    gemm_tc<<<dim3(FF_/256, NT_/128), thr, SMEM_DYN>>>(aoH, aoL, wiH, wiL,
        dpI, NT_, FF_, D_, FF_, NT_, 0, 1);

    // FFN2
    Dest4 dpO;
    dpO.d[0] = { d_tmp, nullptr, nullptr, b_o };
    dpO.d[1] = dpO.d[0]; dpO.d[2] = dpO.d[0]; dpO.d[3] = dpO.d[0];
    gemm_tc<<<dim3(D_/256, NT_/128), thr, SMEM_DYN>>>(intH, intL, woH, woL,
        dpO, NT_, D_, FF_, D_, NT_, 0, 0);

    // final LN -> split (word, entity) output
    ln_kernel<<<NT_, thr>>>(d_tmp, nullptr, nullptr, d_ao, 1, gm_o, bt_o,
                            (float*)d_out, 1, nullptr, nullptr);
}